// round 2
// baseline (speedup 1.0000x reference)
#include <cuda_runtime.h>
#include <cuda_bf16.h>
#include <cstdint>

// EmbeddingBagCollection: F=8 tables [N=200000, D=64] f32, values [F, T=163840] i32,
// offsets [F, B+1=8193] i32 (include_last_offset). Output [B=8192, F*D=512] f32:
// out[b, f*D + d] = sum_{i in [offs[f][b], offs[f][b+1])} tables[f][values[f][i]][d]
//
// Strategy: one warp per (f, b) bag. Lane l accumulates columns {2l, 2l+1} as a
// float2, so each table-row read is a single fully-coalesced 256B transaction
// (2 x 128B lines). Index loop unrolled x4 for MLP. Pure HBM-bound gather.

static constexpr int F = 8;
static constexpr int B = 8192;
static constexpr int N = 200000;
static constexpr int D = 64;
static constexpr int T = 163840;

__global__ __launch_bounds__(256, 8)
void ebc_pool_kernel(const float* __restrict__ tables,
                     const int*   __restrict__ values,
                     const int*   __restrict__ offsets,
                     float*       __restrict__ out)
{
    const int gwarp = (blockIdx.x * blockDim.x + threadIdx.x) >> 5;
    const int lane  = threadIdx.x & 31;
    if (gwarp >= F * B) return;

    const int f = gwarp >> 13;          // B = 8192 = 2^13
    const int b = gwarp & (B - 1);

    const int* __restrict__ offs = offsets + f * (B + 1);
    const int start = __ldg(offs + b);
    const int end   = __ldg(offs + b + 1);

    const int* __restrict__ vals = values + (size_t)f * T;
    // Base pointer for this table, viewed as float2; lane covers element pair `lane`.
    const float2* __restrict__ tab2 =
        reinterpret_cast<const float2*>(tables + (size_t)f * N * D);

    float accx = 0.0f, accy = 0.0f;

    int i = start;
    // Unrolled by 4: four independent row loads in flight per warp iteration.
    for (; i + 4 <= end; i += 4) {
        const int r0 = __ldg(vals + i + 0);
        const int r1 = __ldg(vals + i + 1);
        const int r2 = __ldg(vals + i + 2);
        const int r3 = __ldg(vals + i + 3);
        const float2 v0 = __ldg(tab2 + (size_t)r0 * (D / 2) + lane);
        const float2 v1 = __ldg(tab2 + (size_t)r1 * (D / 2) + lane);
        const float2 v2 = __ldg(tab2 + (size_t)r2 * (D / 2) + lane);
        const float2 v3 = __ldg(tab2 + (size_t)r3 * (D / 2) + lane);
        accx += v0.x + v1.x + v2.x + v3.x;
        accy += v0.y + v1.y + v2.y + v3.y;
    }
    for (; i < end; ++i) {
        const int r = __ldg(vals + i);
        const float2 v = __ldg(tab2 + (size_t)r * (D / 2) + lane);
        accx += v.x;
        accy += v.y;
    }

    // out[b, f*D + 2*lane .. 2*lane+1] — 256B coalesced store per warp.
    float2* __restrict__ o =
        reinterpret_cast<float2*>(out + (size_t)b * (F * D) + f * D);
    o[lane] = make_float2(accx, accy);
}

extern "C" void kernel_launch(void* const* d_in, const int* in_sizes, int n_in,
                              void* d_out, int out_size)
{
    const float* tables  = (const float*)d_in[0];  // [F, N, D]
    const int*   values  = (const int*)  d_in[1];  // [F, T]
    const int*   offsets = (const int*)  d_in[2];  // [F, B+1]
    float*       out     = (float*)d_out;          // [B, F*D]

    const int total_warps = F * B;                 // 65536 bags
    const int threads = 256;                       // 8 warps/block
    const int blocks = (total_warps * 32 + threads - 1) / threads;  // 8192

    ebc_pool_kernel<<<blocks, threads>>>(tables, values, offsets, out);
}

// round 3
// speedup vs baseline: 1.1242x; 1.1242x over previous
#include <cuda_runtime.h>
#include <cuda_bf16.h>
#include <cstdint>

// EmbeddingBagCollection: F=8 tables [N=200000, D=64] f32, values [F, T=163840] i32,
// offsets [F, B+1=8193] i32. Output [B=8192, F*D=512] f32.
//
// One warp per (f, b) bag.
//  - 32 indices prefetched per coalesced LDG, broadcast via shfl (no load chain).
//  - Two rows per warp per load instruction: half-warps split even/odd rows,
//    each lane a float4 (16 lanes x 16B = 256B = one row).
//  - 8-pair unroll -> 8 independent LDG.128 = 16 rows in flight per warp.
//  - shfl_xor(16) merges halves; lanes 0-15 store one coalesced 256B float4 row.

static constexpr int F = 8;
static constexpr int B = 8192;
static constexpr int N = 200000;
static constexpr int D = 64;
static constexpr int T = 163840;
static constexpr unsigned FULL = 0xffffffffu;

__global__ __launch_bounds__(256)
void ebc_pool_kernel(const float* __restrict__ tables,
                     const int*   __restrict__ values,
                     const int*   __restrict__ offsets,
                     float*       __restrict__ out)
{
    const int gwarp = (blockIdx.x * blockDim.x + threadIdx.x) >> 5;
    const int lane  = threadIdx.x & 31;
    if (gwarp >= F * B) return;

    const int f = gwarp >> 13;          // B = 8192 = 2^13
    const int b = gwarp & (B - 1);

    const int half = lane >> 4;         // 0: even rows, 1: odd rows
    const int hl   = lane & 15;         // float4 slot within row

    const int* __restrict__ offs = offsets + f * (B + 1);
    const int start = __ldg(offs + b);
    const int end   = __ldg(offs + b + 1);

    const int* __restrict__ vals = values + (size_t)f * T;
    const float4* __restrict__ tab4 =
        reinterpret_cast<const float4*>(tables + (size_t)f * N * D);  // row stride = 16 float4

    float4 acc = make_float4(0.f, 0.f, 0.f, 0.f);

    int i = start;
    while (i < end) {
        const int chunk = min(32, end - i);
        // Coalesced prefetch of up to 32 indices into registers.
        const int idx = (lane < chunk) ? __ldg(vals + i + lane) : 0;

        int j = 0;
        // 8 pairs (16 rows) per iteration: 8 independent LDG.128 in flight.
        for (; j + 16 <= chunk; j += 16) {
            const int r0 = __shfl_sync(FULL, idx, j +  0 + half);
            const int r1 = __shfl_sync(FULL, idx, j +  2 + half);
            const int r2 = __shfl_sync(FULL, idx, j +  4 + half);
            const int r3 = __shfl_sync(FULL, idx, j +  6 + half);
            const int r4 = __shfl_sync(FULL, idx, j +  8 + half);
            const int r5 = __shfl_sync(FULL, idx, j + 10 + half);
            const int r6 = __shfl_sync(FULL, idx, j + 12 + half);
            const int r7 = __shfl_sync(FULL, idx, j + 14 + half);
            const float4 v0 = __ldg(tab4 + (size_t)r0 * 16 + hl);
            const float4 v1 = __ldg(tab4 + (size_t)r1 * 16 + hl);
            const float4 v2 = __ldg(tab4 + (size_t)r2 * 16 + hl);
            const float4 v3 = __ldg(tab4 + (size_t)r3 * 16 + hl);
            const float4 v4 = __ldg(tab4 + (size_t)r4 * 16 + hl);
            const float4 v5 = __ldg(tab4 + (size_t)r5 * 16 + hl);
            const float4 v6 = __ldg(tab4 + (size_t)r6 * 16 + hl);
            const float4 v7 = __ldg(tab4 + (size_t)r7 * 16 + hl);
            acc.x += v0.x + v1.x + v2.x + v3.x + v4.x + v5.x + v6.x + v7.x;
            acc.y += v0.y + v1.y + v2.y + v3.y + v4.y + v5.y + v6.y + v7.y;
            acc.z += v0.z + v1.z + v2.z + v3.z + v4.z + v5.z + v6.z + v7.z;
            acc.w += v0.w + v1.w + v2.w + v3.w + v4.w + v5.w + v6.w + v7.w;
        }
        // Remaining full pairs (2 rows per load).
        for (; j + 2 <= chunk; j += 2) {
            const int r = __shfl_sync(FULL, idx, j + half);
            const float4 v = __ldg(tab4 + (size_t)r * 16 + hl);
            acc.x += v.x; acc.y += v.y; acc.z += v.z; acc.w += v.w;
        }
        // Singleton row: only even-half loads it.
        if (j < chunk) {
            const int r = __shfl_sync(FULL, idx, j);
            if (half == 0) {
                const float4 v = __ldg(tab4 + (size_t)r * 16 + hl);
                acc.x += v.x; acc.y += v.y; acc.z += v.z; acc.w += v.w;
            }
        }
        i += chunk;
    }

    // Merge even/odd-row partial sums across half-warps.
    acc.x += __shfl_xor_sync(FULL, acc.x, 16);
    acc.y += __shfl_xor_sync(FULL, acc.y, 16);
    acc.z += __shfl_xor_sync(FULL, acc.z, 16);
    acc.w += __shfl_xor_sync(FULL, acc.w, 16);

    // Lanes 0-15 store one coalesced 256B row: out[b, f*D .. f*D+63].
    if (lane < 16) {
        float4* __restrict__ o =
            reinterpret_cast<float4*>(out + (size_t)b * (F * D) + f * D);
        o[hl] = acc;
    }
}

extern "C" void kernel_launch(void* const* d_in, const int* in_sizes, int n_in,
                              void* d_out, int out_size)
{
    const float* tables  = (const float*)d_in[0];  // [F, N, D]
    const int*   values  = (const int*)  d_in[1];  // [F, T]
    const int*   offsets = (const int*)  d_in[2];  // [F, B+1]
    float*       out     = (float*)d_out;          // [B, F*D]

    const int total_warps = F * B;                 // 65536 bags
    const int threads = 256;                       // 8 warps/block
    const int blocks = (total_warps * 32 + threads - 1) / threads;  // 8192

    ebc_pool_kernel<<<blocks, threads>>>(tables, values, offsets, out);
}